// round 4
// baseline (speedup 1.0000x reference)
#include <cuda_runtime.h>
#include <math_constants.h>

#define NROWS 65536
#define DDIM  256
#define KCB   1024
#define NCB   3

#define BM 64
#define BN 128
#define BK 32
#define NTHREADS 256

// ---------------- scratch (no allocations allowed) ----------------
__device__ float  g_res[(size_t)NROWS * DDIM];   // residual between stages (64 MB)
__device__ float  g_c2[NCB * KCB];               // per-stage ||c_k||^2
__device__ double g_loss[NCB];                   // per-stage sum of (code - r)^2

// ---------------- smem layout (floats) ----------------
// zT   : [256][68]   transposed z tile
// cbs  : [32][192]   codebook sub-tile, d-major, k padded: pos(k)= (k>>3)*12 + (k&7)
//                    (16 chunks * 12 floats = 192 floats per d-row; chunk c's float4
//                     pair lands on banks 12c mod 32 -> c=0..7 cover all 32 banks once,
//                     c=8..15 repeat -> LDS.128 = 2 conflict-free wavefronts)
// c2sh : [1024]
// l2s  : [64]
// redS : [64*16], redI: [64*16], bidx: [64]
#define ZT_STRIDE 68
#define CB_STRIDE 192
#define OFF_ZT    0
#define OFF_CBS   (OFF_ZT   + 256 * ZT_STRIDE)        // 17408
#define OFF_C2    (OFF_CBS  + 32 * CB_STRIDE)         // 23552
#define OFF_L2    (OFF_C2   + 1024)                   // 24576
#define OFF_REDS  (OFF_L2   + 64)                     // 24640
#define OFF_REDI  (OFF_REDS + 64 * 16)                // 25664
#define OFF_BIDX  (OFF_REDI + 64 * 16)                // 26688
#define SMEM_FLOATS (OFF_BIDX + 64)                   // 26752
#define SMEM_BYTES  (SMEM_FLOATS * 4)                 // 107008

// ---------------- init: zero loss accumulators, compute c2 ----------------
__global__ void rvq_init_kernel(const float* __restrict__ cb,
                                float* __restrict__ c2out,
                                double* __restrict__ loss)
{
    if (blockIdx.x == 0 && threadIdx.x < NCB) loss[threadIdx.x] = 0.0;

    int gw   = (blockIdx.x * blockDim.x + threadIdx.x) >> 5;  // one warp per codeword
    int lane = threadIdx.x & 31;
    if (gw < NCB * KCB) {
        const float* row = cb + (size_t)gw * DDIM;
        float s = 0.f;
        for (int d = lane; d < DDIM; d += 32) { float v = row[d]; s = fmaf(v, v, s); }
        #pragma unroll
        for (int o = 16; o; o >>= 1) s += __shfl_xor_sync(0xffffffffu, s, o);
        if (lane == 0) c2out[gw] = s;
    }
}

// ---------------- fused stage: GEMM + argmin + gather/update/loss ----------------
__global__ __launch_bounds__(NTHREADS, 2)
void rvq_stage_kernel(const float* __restrict__ zin,   // residual input [N,D]
                      const float* __restrict__ cbg,   // codebook (stage offset applied) [K,D]
                      const float* __restrict__ c2g,   // stage c2 [K]
                      float* __restrict__ fq,          // output quantized [N,D]
                      float* __restrict__ rout,        // residual output [N,D]
                      double* __restrict__ lossp,      // stage loss accumulator
                      int firstStage, int writeR)
{
    extern __shared__ float sm[];
    float* zT   = sm + OFF_ZT;
    float* cbs  = sm + OFF_CBS;
    float* c2sh = sm + OFF_C2;
    float* l2s  = sm + OFF_L2;
    float* redS = sm + OFF_REDS;
    int*   redI = (int*)(sm + OFF_REDI);
    int*   bidx = (int*)(sm + OFF_BIDX);

    const int tid = threadIdx.x;
    const int m0  = blockIdx.x * BM;
    const int tx  = tid & 15;   // 0..15 -> k chunk: k = tx*8 + j (j=0..7)
    const int ty  = tid >> 4;   // 0..15 -> rows 4*ty..4*ty+3

    // ---- load z tile transposed into smem (coalesced float4 reads) ----
    #pragma unroll
    for (int it = 0; it < 16; ++it) {
        int f  = tid + it * NTHREADS;          // 0..4095
        int m  = f >> 6;                       // row 0..63
        int d4 = f & 63;                       // float4 index along D
        float4 v = *(const float4*)(zin + (size_t)(m0 + m) * DDIM + d4 * 4);
        zT[(d4 * 4 + 0) * ZT_STRIDE + m] = v.x;
        zT[(d4 * 4 + 1) * ZT_STRIDE + m] = v.y;
        zT[(d4 * 4 + 2) * ZT_STRIDE + m] = v.z;
        zT[(d4 * 4 + 3) * ZT_STRIDE + m] = v.w;
    }
    // ---- stage c2 into smem ----
    #pragma unroll
    for (int i = tid; i < KCB; i += NTHREADS) c2sh[i] = c2g[i];
    __syncthreads();

    // ---- l2 per row (same sequential fp32 chain as before) ----
    if (tid < BM) {
        float s = 0.f;
        for (int d = 0; d < DDIM; ++d) { float v = zT[d * ZT_STRIDE + tid]; s = fmaf(v, v, s); }
        l2s[tid] = s;
    }
    __syncthreads();

    // loader mapping: kl = tid&31 (k low), dc = tid>>5 (d float4 chunk 0..7)
    const int kl = tid & 31;
    const int dc = tid >> 5;

    // ---- GEMM + argmin over K in tiles of BN ----
    float best[4];
    int   bi[4];
    #pragma unroll
    for (int r = 0; r < 4; ++r) { best[r] = CUDART_INF_F; bi[r] = 0; }

    for (int kt = 0; kt < KCB / BN; ++kt) {
        float acc[4][8];
        #pragma unroll
        for (int r = 0; r < 4; ++r)
            #pragma unroll
            for (int j = 0; j < 8; ++j) acc[r][j] = 0.f;

        for (int dt = 0; dt < DDIM / BK; ++dt) {
            // load cb sub-tile [BN k][BK d] transposed into cbs[d][pos(k)]
            {
                #pragma unroll
                for (int kk = 0; kk < 4; ++kk) {
                    int k  = kl + kk * 32;
                    int pk = ((k >> 3) * 12) + (k & 7);
                    float4 v = *(const float4*)(cbg + (size_t)(kt * BN + k) * DDIM + dt * BK + dc * 4);
                    cbs[(dc * 4 + 0) * CB_STRIDE + pk] = v.x;
                    cbs[(dc * 4 + 1) * CB_STRIDE + pk] = v.y;
                    cbs[(dc * 4 + 2) * CB_STRIDE + pk] = v.z;
                    cbs[(dc * 4 + 3) * CB_STRIDE + pk] = v.w;
                }
            }
            __syncthreads();

            #pragma unroll
            for (int d = 0; d < BK; ++d) {
                float4 zv  = *(const float4*)&zT[(dt * BK + d) * ZT_STRIDE + ty * 4];
                float4 ca  = *(const float4*)&cbs[d * CB_STRIDE + tx * 12];
                float4 cb4 = *(const float4*)&cbs[d * CB_STRIDE + tx * 12 + 4];
                // j = 0..3 <- ca, j = 4..7 <- cb4 ; identical FMA chain per (row,k) as R1
                acc[0][0] = fmaf(zv.x, ca.x,  acc[0][0]);
                acc[1][0] = fmaf(zv.y, ca.x,  acc[1][0]);
                acc[2][0] = fmaf(zv.z, ca.x,  acc[2][0]);
                acc[3][0] = fmaf(zv.w, ca.x,  acc[3][0]);
                acc[0][1] = fmaf(zv.x, ca.y,  acc[0][1]);
                acc[1][1] = fmaf(zv.y, ca.y,  acc[1][1]);
                acc[2][1] = fmaf(zv.z, ca.y,  acc[2][1]);
                acc[3][1] = fmaf(zv.w, ca.y,  acc[3][1]);
                acc[0][2] = fmaf(zv.x, ca.z,  acc[0][2]);
                acc[1][2] = fmaf(zv.y, ca.z,  acc[1][2]);
                acc[2][2] = fmaf(zv.z, ca.z,  acc[2][2]);
                acc[3][2] = fmaf(zv.w, ca.z,  acc[3][2]);
                acc[0][3] = fmaf(zv.x, ca.w,  acc[0][3]);
                acc[1][3] = fmaf(zv.y, ca.w,  acc[1][3]);
                acc[2][3] = fmaf(zv.z, ca.w,  acc[2][3]);
                acc[3][3] = fmaf(zv.w, ca.w,  acc[3][3]);
                acc[0][4] = fmaf(zv.x, cb4.x, acc[0][4]);
                acc[1][4] = fmaf(zv.y, cb4.x, acc[1][4]);
                acc[2][4] = fmaf(zv.z, cb4.x, acc[2][4]);
                acc[3][4] = fmaf(zv.w, cb4.x, acc[3][4]);
                acc[0][5] = fmaf(zv.x, cb4.y, acc[0][5]);
                acc[1][5] = fmaf(zv.y, cb4.y, acc[1][5]);
                acc[2][5] = fmaf(zv.z, cb4.y, acc[2][5]);
                acc[3][5] = fmaf(zv.w, cb4.y, acc[3][5]);
                acc[0][6] = fmaf(zv.x, cb4.z, acc[0][6]);
                acc[1][6] = fmaf(zv.y, cb4.z, acc[1][6]);
                acc[2][6] = fmaf(zv.z, cb4.z, acc[2][6]);
                acc[3][6] = fmaf(zv.w, cb4.z, acc[3][6]);
                acc[0][7] = fmaf(zv.x, cb4.w, acc[0][7]);
                acc[1][7] = fmaf(zv.y, cb4.w, acc[1][7]);
                acc[2][7] = fmaf(zv.z, cb4.w, acc[2][7]);
                acc[3][7] = fmaf(zv.w, cb4.w, acc[3][7]);
            }
            __syncthreads();
        }

        // fold distances (replicating reference rounding: (l2 - 2*cl) + c2)
        #pragma unroll
        for (int r = 0; r < 4; ++r) {
            float l2v = l2s[ty * 4 + r];
            #pragma unroll
            for (int j = 0; j < 8; ++j) {
                int kg = kt * BN + tx * 8 + j;            // ascending within thread
                float s = (l2v - 2.0f * acc[r][j]) + c2sh[kg];
                if (s < best[r]) { best[r] = s; bi[r] = kg; }
            }
        }
    }

    // ---- cross-thread argmin per row (first-index tie break) ----
    #pragma unroll
    for (int r = 0; r < 4; ++r) {
        redS[(ty * 4 + r) * 16 + tx] = best[r];
        redI[(ty * 4 + r) * 16 + tx] = bi[r];
    }
    __syncthreads();
    if (tid < BM) {
        float b  = redS[tid * 16];
        int   ib = redI[tid * 16];
        #pragma unroll
        for (int t = 1; t < 16; ++t) {
            float s  = redS[tid * 16 + t];
            int   i2 = redI[tid * 16 + t];
            if (s < b || (s == b && i2 < ib)) { b = s; ib = i2; }
        }
        bidx[tid] = ib;
    }
    __syncthreads();

    // ---- update: gather code, straight-through fq, residual, loss ----
    double lacc = 0.0;
    #pragma unroll
    for (int it = 0; it < 16; ++it) {
        int f  = tid + it * NTHREADS;
        int m  = f >> 6;
        int d4 = f & 63;
        size_t off = (size_t)(m0 + m) * DDIM + d4 * 4;
        float4 r4 = *(const float4*)(zin + off);
        float4 c4 = *(const float4*)(cbg + (size_t)bidx[m] * DDIM + d4 * 4);
        float4 fo, rn;
        float4 fprev;
        if (!firstStage) fprev = *(const float4*)(fq + off);

        // exact reference rounding chain per element:
        // t = c - r; st = r + t; fq (+)= st; r_next = r - st; loss += t*t
        {
            float t = c4.x - r4.x; float st = r4.x + t;
            fo.x = firstStage ? st : (fprev.x + st); rn.x = r4.x - st;
            lacc += (double)t * (double)t;
        }
        {
            float t = c4.y - r4.y; float st = r4.y + t;
            fo.y = firstStage ? st : (fprev.y + st); rn.y = r4.y - st;
            lacc += (double)t * (double)t;
        }
        {
            float t = c4.z - r4.z; float st = r4.z + t;
            fo.z = firstStage ? st : (fprev.z + st); rn.z = r4.z - st;
            lacc += (double)t * (double)t;
        }
        {
            float t = c4.w - r4.w; float st = r4.w + t;
            fo.w = firstStage ? st : (fprev.w + st); rn.w = r4.w - st;
            lacc += (double)t * (double)t;
        }
        *(float4*)(fq + off) = fo;
        if (writeR) *(float4*)(rout + off) = rn;
    }

    // warp-reduce loss, one atomic per warp
    #pragma unroll
    for (int o = 16; o; o >>= 1) lacc += __shfl_down_sync(0xffffffffu, lacc, o);
    if ((tid & 31) == 0) atomicAdd(lossp, lacc);
}

// ---------------- finalize: write the two (identical) loss scalars ----------------
__global__ void rvq_finalize_kernel(const double* __restrict__ loss, float* __restrict__ out)
{
    if (blockIdx.x == 0 && threadIdx.x == 0) {
        const double nd = (double)((size_t)NROWS * DDIM);
        float L = 0.f;
        for (int i = 0; i < NCB; ++i) L = L + (float)(loss[i] / nd);  // per-stage mean, summed in fp32 like ref
        out[(size_t)NROWS * DDIM]     = L;  // codebook_losses
        out[(size_t)NROWS * DDIM + 1] = L;  // commitment_losses (numerically identical forward)
    }
}

// ---------------- launch ----------------
extern "C" void kernel_launch(void* const* d_in, const int* in_sizes, int n_in,
                              void* d_out, int out_size)
{
    const float* z  = (const float*)d_in[0];   // [65536, 256]
    const float* cb = (const float*)d_in[1];   // [3, 1024, 256]
    float* out = (float*)d_out;

    float*  res_p  = nullptr;
    float*  c2_p   = nullptr;
    double* loss_p = nullptr;
    cudaGetSymbolAddress((void**)&res_p,  g_res);
    cudaGetSymbolAddress((void**)&c2_p,   g_c2);
    cudaGetSymbolAddress((void**)&loss_p, g_loss);

    cudaFuncSetAttribute(rvq_stage_kernel,
                         cudaFuncAttributeMaxDynamicSharedMemorySize, SMEM_BYTES);

    const int nblk = NROWS / BM;  // 1024

    rvq_init_kernel<<<(NCB * KCB * 32) / NTHREADS, NTHREADS>>>(cb, c2_p, loss_p);

    // stage 0: reads z, writes fq (init) + residual
    rvq_stage_kernel<<<nblk, NTHREADS, SMEM_BYTES>>>(
        z, cb, c2_p, out, res_p, loss_p + 0, /*firstStage=*/1, /*writeR=*/1);
    // stage 1: in-place residual (rows block-exclusive, read-before-write)
    rvq_stage_kernel<<<nblk, NTHREADS, SMEM_BYTES>>>(
        res_p, cb + (size_t)KCB * DDIM, c2_p + KCB, out, res_p, loss_p + 1, 0, 1);
    // stage 2: residual output unused -> skip write
    rvq_stage_kernel<<<nblk, NTHREADS, SMEM_BYTES>>>(
        res_p, cb + (size_t)2 * KCB * DDIM, c2_p + 2 * KCB, out, res_p, loss_p + 2, 0, 0);

    rvq_finalize_kernel<<<1, 32>>>(loss_p, out);
}

// round 5
// speedup vs baseline: 1.1972x; 1.1972x over previous
#include <cuda_runtime.h>
#include <math_constants.h>

#define NROWS 65536
#define DDIM  256
#define KCB   1024
#define NCB   3

#define BM 64
#define BN 128
#define BK 32
#define NTHREADS 256

// ---------------- scratch (no allocations allowed) ----------------
__device__ float  g_res[(size_t)NROWS * DDIM];   // residual between stages (64 MB)
__device__ float  g_c2[NCB * KCB];               // per-stage ||c_k||^2
__device__ double g_loss[NCB];                   // per-stage sum of (code - r)^2

// ---------------- smem layout (floats) ----------------
// zT   : [256][68]   transposed z tile (row-major by d; row index = local m)
// cbs  : [32][128]   codebook sub-tile, d-major, plain layout cbs[d][k]
// c2sh : [1024]
// l2s  : [64]
// redS : [64][33], redI : [64][33]  (stride 33 -> conflict-free reduction)
// bidx : [64]
#define ZT_STRIDE 68
#define CBS 128
#define OFF_ZT    0
#define OFF_CBS   (OFF_ZT   + 256 * ZT_STRIDE)        // 17408
#define OFF_C2    (OFF_CBS  + 32 * CBS)               // 21504
#define OFF_L2    (OFF_C2   + 1024)                   // 22528
#define OFF_REDS  (OFF_L2   + 64)                     // 22592
#define OFF_REDI  (OFF_REDS + 64 * 33)                // 24704
#define OFF_BIDX  (OFF_REDI + 64 * 33)                // 26816
#define SMEM_FLOATS (OFF_BIDX + 64)                   // 26880
#define SMEM_BYTES  (SMEM_FLOATS * 4)                 // 107520

// ---------------- init: zero loss accumulators, compute c2 ----------------
__global__ void rvq_init_kernel(const float* __restrict__ cb,
                                float* __restrict__ c2out,
                                double* __restrict__ loss)
{
    if (blockIdx.x == 0 && threadIdx.x < NCB) loss[threadIdx.x] = 0.0;

    int gw   = (blockIdx.x * blockDim.x + threadIdx.x) >> 5;  // one warp per codeword
    int lane = threadIdx.x & 31;
    if (gw < NCB * KCB) {
        const float* row = cb + (size_t)gw * DDIM;
        float s = 0.f;
        for (int d = lane; d < DDIM; d += 32) { float v = row[d]; s = fmaf(v, v, s); }
        #pragma unroll
        for (int o = 16; o; o >>= 1) s += __shfl_xor_sync(0xffffffffu, s, o);
        if (lane == 0) c2out[gw] = s;
    }
}

// ---------------- fused stage: GEMM + argmin + gather/update/loss ----------------
__global__ __launch_bounds__(NTHREADS, 2)
void rvq_stage_kernel(const float* __restrict__ zin,   // residual input [N,D]
                      const float* __restrict__ cbg,   // codebook (stage offset applied) [K,D]
                      const float* __restrict__ c2g,   // stage c2 [K]
                      float* __restrict__ fq,          // output quantized [N,D]
                      float* __restrict__ rout,        // residual output [N,D]
                      double* __restrict__ lossp,      // stage loss accumulator
                      int firstStage, int writeR)
{
    extern __shared__ float sm[];
    float* zT   = sm + OFF_ZT;
    float* cbs  = sm + OFF_CBS;
    float* c2sh = sm + OFF_C2;
    float* l2s  = sm + OFF_L2;
    float* redS = sm + OFF_REDS;
    int*   redI = (int*)(sm + OFF_REDI);
    int*   bidx = (int*)(sm + OFF_BIDX);

    const int tid = threadIdx.x;
    const int m0  = blockIdx.x * BM;
    const int tx  = tid & 31;   // k lane: k = tx + 32*j, j=0..3 (32 distinct banks/warp)
    const int ty  = tid >> 5;   // warp id: owns rows ty*8 .. ty*8+7

    // ---- load z tile transposed into smem (coalesced float4 reads) ----
    #pragma unroll
    for (int it = 0; it < 16; ++it) {
        int f  = tid + it * NTHREADS;          // 0..4095
        int m  = f >> 6;                       // row 0..63
        int d4 = f & 63;                       // float4 index along D
        float4 v = *(const float4*)(zin + (size_t)(m0 + m) * DDIM + d4 * 4);
        zT[(d4 * 4 + 0) * ZT_STRIDE + m] = v.x;
        zT[(d4 * 4 + 1) * ZT_STRIDE + m] = v.y;
        zT[(d4 * 4 + 2) * ZT_STRIDE + m] = v.z;
        zT[(d4 * 4 + 3) * ZT_STRIDE + m] = v.w;
    }
    // ---- stage c2 into smem ----
    #pragma unroll
    for (int i = tid; i < KCB; i += NTHREADS) c2sh[i] = c2g[i];
    __syncthreads();

    // ---- l2 per row (same sequential fp32 chain as reference) ----
    if (tid < BM) {
        float s = 0.f;
        for (int d = 0; d < DDIM; ++d) { float v = zT[d * ZT_STRIDE + tid]; s = fmaf(v, v, s); }
        l2s[tid] = s;
    }
    __syncthreads();

    // loader mapping for cbs: kload = tid & 127, dhalf = tid >> 7
    const int kload = tid & 127;
    const int dhalf = tid >> 7;

    // ---- GEMM + argmin over K in tiles of BN ----
    float best[8];
    int   bi[8];
    #pragma unroll
    for (int r = 0; r < 8; ++r) { best[r] = CUDART_INF_F; bi[r] = 0; }

    for (int kt = 0; kt < KCB / BN; ++kt) {
        float acc[8][4];
        #pragma unroll
        for (int r = 0; r < 8; ++r)
            #pragma unroll
            for (int j = 0; j < 4; ++j) acc[r][j] = 0.f;

        for (int dt = 0; dt < DDIM / BK; ++dt) {
            // load cb sub-tile [BN k][BK d] transposed into cbs[d][k]
            // STS: within a warp all lanes have distinct kload -> 32 banks, conflict-free
            {
                const float* src = cbg + (size_t)(kt * BN + kload) * DDIM + dt * BK + dhalf * 16;
                #pragma unroll
                for (int i = 0; i < 4; ++i) {
                    float4 v = *(const float4*)(src + i * 4);
                    int d = dhalf * 16 + i * 4;
                    cbs[(d + 0) * CBS + kload] = v.x;
                    cbs[(d + 1) * CBS + kload] = v.y;
                    cbs[(d + 2) * CBS + kload] = v.z;
                    cbs[(d + 3) * CBS + kload] = v.w;
                }
            }
            __syncthreads();

            #pragma unroll
            for (int d = 0; d < BK; ++d) {
                int dg = dt * BK + d;
                // z: both LDS.128 are all-lanes-same-address broadcasts (1 wf each)
                float4 za = *(const float4*)&zT[dg * ZT_STRIDE + ty * 8];
                float4 zb = *(const float4*)&zT[dg * ZT_STRIDE + ty * 8 + 4];
                // cb: 4x LDS.32, lanes span 32 distinct banks (full 128B unique per wf)
                float c0 = cbs[d * CBS + tx];
                float c1 = cbs[d * CBS + tx + 32];
                float c2v = cbs[d * CBS + tx + 64];
                float c3 = cbs[d * CBS + tx + 96];
                float zr[8] = {za.x, za.y, za.z, za.w, zb.x, zb.y, zb.z, zb.w};
                float cc[4] = {c0, c1, c2v, c3};
                #pragma unroll
                for (int r = 0; r < 8; ++r)
                    #pragma unroll
                    for (int j = 0; j < 4; ++j)
                        acc[r][j] = fmaf(zr[r], cc[j], acc[r][j]);
            }
            __syncthreads();
        }

        // fold distances (reference rounding: (l2 - 2*cl) + c2), ascending k per thread
        #pragma unroll
        for (int r = 0; r < 8; ++r) {
            float l2v = l2s[ty * 8 + r];
            #pragma unroll
            for (int j = 0; j < 4; ++j) {
                int kg = kt * BN + tx + 32 * j;
                float s = (l2v - 2.0f * acc[r][j]) + c2sh[kg];
                if (s < best[r]) { best[r] = s; bi[r] = kg; }
            }
        }
    }

    // ---- cross-thread argmin per row (first-index tie break) ----
    #pragma unroll
    for (int r = 0; r < 8; ++r) {
        int row = ty * 8 + r;
        redS[row * 33 + tx] = best[r];
        redI[row * 33 + tx] = bi[r];
    }
    __syncthreads();
    if (tid < BM) {
        float b  = redS[tid * 33];
        int   ib = redI[tid * 33];
        #pragma unroll
        for (int t = 1; t < 32; ++t) {
            float s  = redS[tid * 33 + t];
            int   i2 = redI[tid * 33 + t];
            if (s < b || (s == b && i2 < ib)) { b = s; ib = i2; }
        }
        bidx[tid] = ib;
    }
    __syncthreads();

    // ---- update: gather code, straight-through fq, residual, loss ----
    double lacc = 0.0;
    #pragma unroll
    for (int it = 0; it < 16; ++it) {
        int f  = tid + it * NTHREADS;
        int m  = f >> 6;
        int d4 = f & 63;
        size_t off = (size_t)(m0 + m) * DDIM + d4 * 4;
        float4 r4 = *(const float4*)(zin + off);
        float4 c4 = *(const float4*)(cbg + (size_t)bidx[m] * DDIM + d4 * 4);
        float4 fo, rn;
        float4 fprev;
        if (!firstStage) fprev = *(const float4*)(fq + off);

        // exact reference rounding chain per element:
        // t = c - r; st = r + t; fq (+)= st; r_next = r - st; loss += t*t
        {
            float t = c4.x - r4.x; float st = r4.x + t;
            fo.x = firstStage ? st : (fprev.x + st); rn.x = r4.x - st;
            lacc += (double)t * (double)t;
        }
        {
            float t = c4.y - r4.y; float st = r4.y + t;
            fo.y = firstStage ? st : (fprev.y + st); rn.y = r4.y - st;
            lacc += (double)t * (double)t;
        }
        {
            float t = c4.z - r4.z; float st = r4.z + t;
            fo.z = firstStage ? st : (fprev.z + st); rn.z = r4.z - st;
            lacc += (double)t * (double)t;
        }
        {
            float t = c4.w - r4.w; float st = r4.w + t;
            fo.w = firstStage ? st : (fprev.w + st); rn.w = r4.w - st;
            lacc += (double)t * (double)t;
        }
        *(float4*)(fq + off) = fo;
        if (writeR) *(float4*)(rout + off) = rn;
    }

    // warp-reduce loss, one atomic per warp
    #pragma unroll
    for (int o = 16; o; o >>= 1) lacc += __shfl_down_sync(0xffffffffu, lacc, o);
    if ((tid & 31) == 0) atomicAdd(lossp, lacc);
}

// ---------------- finalize: write the two (identical) loss scalars ----------------
__global__ void rvq_finalize_kernel(const double* __restrict__ loss, float* __restrict__ out)
{
    if (blockIdx.x == 0 && threadIdx.x == 0) {
        const double nd = (double)((size_t)NROWS * DDIM);
        float L = 0.f;
        for (int i = 0; i < NCB; ++i) L = L + (float)(loss[i] / nd);  // per-stage mean, summed in fp32 like ref
        out[(size_t)NROWS * DDIM]     = L;  // codebook_losses
        out[(size_t)NROWS * DDIM + 1] = L;  // commitment_losses (numerically identical forward)
    }
}

// ---------------- launch ----------------
extern "C" void kernel_launch(void* const* d_in, const int* in_sizes, int n_in,
                              void* d_out, int out_size)
{
    const float* z  = (const float*)d_in[0];   // [65536, 256]
    const float* cb = (const float*)d_in[1];   // [3, 1024, 256]
    float* out = (float*)d_out;

    float*  res_p  = nullptr;
    float*  c2_p   = nullptr;
    double* loss_p = nullptr;
    cudaGetSymbolAddress((void**)&res_p,  g_res);
    cudaGetSymbolAddress((void**)&c2_p,   g_c2);
    cudaGetSymbolAddress((void**)&loss_p, g_loss);

    cudaFuncSetAttribute(rvq_stage_kernel,
                         cudaFuncAttributeMaxDynamicSharedMemorySize, SMEM_BYTES);

    const int nblk = NROWS / BM;  // 1024

    rvq_init_kernel<<<(NCB * KCB * 32) / NTHREADS, NTHREADS>>>(cb, c2_p, loss_p);

    // stage 0: reads z, writes fq (init) + residual
    rvq_stage_kernel<<<nblk, NTHREADS, SMEM_BYTES>>>(
        z, cb, c2_p, out, res_p, loss_p + 0, /*firstStage=*/1, /*writeR=*/1);
    // stage 1: in-place residual (rows block-exclusive, read-before-write)
    rvq_stage_kernel<<<nblk, NTHREADS, SMEM_BYTES>>>(
        res_p, cb + (size_t)KCB * DDIM, c2_p + KCB, out, res_p, loss_p + 1, 0, 1);
    // stage 2: residual output unused -> skip write
    rvq_stage_kernel<<<nblk, NTHREADS, SMEM_BYTES>>>(
        res_p, cb + (size_t)2 * KCB * DDIM, c2_p + 2 * KCB, out, res_p, loss_p + 2, 0, 0);

    rvq_finalize_kernel<<<1, 32>>>(loss_p, out);
}

// round 9
// speedup vs baseline: 1.3197x; 1.1023x over previous
#include <cuda_runtime.h>
#include <math_constants.h>

#define NROWS 65536
#define DDIM  256
#define KCB   1024
#define NCB   3

#define BM 64
#define BN 256
#define BK 16
#define NTHREADS 256

// ---------------- scratch (no allocations allowed) ----------------
__device__ float  g_res[(size_t)NROWS * DDIM];   // residual between stages (64 MB)
__device__ float  g_c2[NCB * KCB];               // per-stage ||c_k||^2
__device__ double g_loss[NCB];                   // per-stage sum of (code - r)^2

// ---------------- packed f32x2 helpers (sm_103a FFMA2 path) ----------------
#define FMA2(acc, a, b) \
    asm("fma.rn.f32x2 %0, %1, %2, %0;" : "+l"(acc) : "l"(a), "l"(b))
#define PACK2(out, lo, hi) \
    asm("mov.b64 %0, {%1, %2};" : "=l"(out) : "r"(__float_as_uint(lo)), "r"(__float_as_uint(hi)))
#define UNPACK2(lo, hi, in) \
    asm("mov.b64 {%0, %1}, %2;" : "=r"(lo), "=r"(hi) : "l"(in))

// ---------------- smem layout (floats) ----------------
// zT   : [256][68]  transposed z tile (d-major, local row index)
// cbs  : [16][256]  codebook sub-tile, d-major, plain cbs[d][k]
// c2sh : [1024]
// l2s  : [64]
// redS : [64][33], redI : [64][33]  (stride 33 -> conflict-free reduction)
// bidx : [64]
#define ZT_STRIDE 68
#define OFF_ZT    0
#define OFF_CBS   (OFF_ZT   + 256 * ZT_STRIDE)        // 17408
#define OFF_C2    (OFF_CBS  + BK * BN)                // 21504
#define OFF_L2    (OFF_C2   + 1024)                   // 22528
#define OFF_REDS  (OFF_L2   + 64)                     // 22592
#define OFF_REDI  (OFF_REDS + 64 * 33)                // 24704
#define OFF_BIDX  (OFF_REDI + 64 * 33)                // 26816
#define SMEM_FLOATS (OFF_BIDX + 64)                   // 26880
#define SMEM_BYTES  (SMEM_FLOATS * 4)                 // 107520 -> 2 blocks/SM

// ---------------- init: zero loss accumulators, compute c2 ----------------
__global__ void rvq_init_kernel(const float* __restrict__ cb,
                                float* __restrict__ c2out,
                                double* __restrict__ loss)
{
    if (blockIdx.x == 0 && threadIdx.x < NCB) loss[threadIdx.x] = 0.0;

    int gw   = (blockIdx.x * blockDim.x + threadIdx.x) >> 5;  // one warp per codeword
    int lane = threadIdx.x & 31;
    if (gw < NCB * KCB) {
        const float* row = cb + (size_t)gw * DDIM;
        float s = 0.f;
        for (int d = lane; d < DDIM; d += 32) { float v = row[d]; s = fmaf(v, v, s); }
        #pragma unroll
        for (int o = 16; o; o >>= 1) s += __shfl_xor_sync(0xffffffffu, s, o);
        if (lane == 0) c2out[gw] = s;
    }
}

// ---------------- fused stage: GEMM + argmin + gather/update/loss ----------------
__global__ __launch_bounds__(NTHREADS, 2)
void rvq_stage_kernel(const float* __restrict__ zin,   // residual input [N,D]
                      const float* __restrict__ cbg,   // codebook (stage offset applied) [K,D]
                      const float* __restrict__ c2g,   // stage c2 [K]
                      float* __restrict__ fq,          // output quantized [N,D]
                      float* __restrict__ rout,        // residual output [N,D]
                      double* __restrict__ lossp,      // stage loss accumulator
                      int firstStage, int writeR)
{
    extern __shared__ float sm[];
    float* zT   = sm + OFF_ZT;
    float* cbs  = sm + OFF_CBS;
    float* c2sh = sm + OFF_C2;
    float* l2s  = sm + OFF_L2;
    float* redS = sm + OFF_REDS;
    int*   redI = (int*)(sm + OFF_REDI);
    int*   bidx = (int*)(sm + OFF_BIDX);

    const int tid = threadIdx.x;
    const int m0  = blockIdx.x * BM;
    const int tx  = tid & 31;   // lane: k = tx*4+{0..3} and 128+tx*4+{0..3}
    const int ty  = tid >> 5;   // warp id: owns rows ty*8 .. ty*8+7

    // ---- load z tile transposed into smem (coalesced float4 reads) ----
    #pragma unroll
    for (int it = 0; it < 16; ++it) {
        int f  = tid + it * NTHREADS;          // 0..4095
        int m  = f >> 6;                       // row 0..63
        int d4 = f & 63;                       // float4 index along D
        float4 v = *(const float4*)(zin + (size_t)(m0 + m) * DDIM + d4 * 4);
        zT[(d4 * 4 + 0) * ZT_STRIDE + m] = v.x;
        zT[(d4 * 4 + 1) * ZT_STRIDE + m] = v.y;
        zT[(d4 * 4 + 2) * ZT_STRIDE + m] = v.z;
        zT[(d4 * 4 + 3) * ZT_STRIDE + m] = v.w;
    }
    // ---- stage c2 into smem ----
    #pragma unroll
    for (int i = tid; i < KCB; i += NTHREADS) c2sh[i] = c2g[i];
    __syncthreads();

    // ---- l2 per row (same sequential fp32 chain as reference) ----
    if (tid < BM) {
        float s = 0.f;
        for (int d = 0; d < DDIM; ++d) { float v = zT[d * ZT_STRIDE + tid]; s = fmaf(v, v, s); }
        l2s[tid] = s;
    }
    __syncthreads();

    // ---- GEMM + argmin over K in 4 tiles of BN=256 ----
    float best[8];
    int   bi[8];
    #pragma unroll
    for (int r = 0; r < 8; ++r) { best[r] = CUDART_INF_F; bi[r] = 0; }

    for (int kt = 0; kt < KCB / BN; ++kt) {
        unsigned long long acc2[8][4];   // [row][pair]; pair jj: k = tx*4+2jj(+1) for jj<2, 128+tx*4+2(jj-2)(+1) else
        #pragma unroll
        for (int r = 0; r < 8; ++r)
            #pragma unroll
            for (int j = 0; j < 4; ++j) acc2[r][j] = 0ULL;

        for (int dt = 0; dt < DDIM / BK; ++dt) {
            // load cb sub-tile [BN k][BK d] transposed into cbs[d][k]
            // thread tid owns k-row (kt*BN + tid); distinct k mod 32 per lane -> conflict-free STS
            {
                const float* src = cbg + (size_t)(kt * BN + tid) * DDIM + dt * BK;
                #pragma unroll
                for (int i = 0; i < 4; ++i) {
                    float4 v = *(const float4*)(src + i * 4);
                    int d = i * 4;
                    cbs[(d + 0) * BN + tid] = v.x;
                    cbs[(d + 1) * BN + tid] = v.y;
                    cbs[(d + 2) * BN + tid] = v.z;
                    cbs[(d + 3) * BN + tid] = v.w;
                }
            }
            __syncthreads();

            #pragma unroll
            for (int d = 0; d < BK; ++d) {
                int dg = dt * BK + d;
                // z: two broadcast LDS.128 (warp's 8 rows)
                float4 za = *(const float4*)&zT[dg * ZT_STRIDE + ty * 8];
                float4 zb = *(const float4*)&zT[dg * ZT_STRIDE + ty * 8 + 4];
                // cb: two contiguous-warp LDS.128 (512B each, conflict-free phases)
                float4 c0 = *(const float4*)&cbs[d * BN + tx * 4];
                float4 c1 = *(const float4*)&cbs[d * BN + 128 + tx * 4];
                unsigned long long cp0, cp1, cp2, cp3;
                PACK2(cp0, c0.x, c0.y);
                PACK2(cp1, c0.z, c0.w);
                PACK2(cp2, c1.x, c1.y);
                PACK2(cp3, c1.z, c1.w);
                float zr[8] = {za.x, za.y, za.z, za.w, zb.x, zb.y, zb.z, zb.w};
                #pragma unroll
                for (int r = 0; r < 8; ++r) {
                    unsigned long long zd;
                    PACK2(zd, zr[r], zr[r]);
                    FMA2(acc2[r][0], zd, cp0);
                    FMA2(acc2[r][1], zd, cp1);
                    FMA2(acc2[r][2], zd, cp2);
                    FMA2(acc2[r][3], zd, cp3);
                }
            }
            __syncthreads();
        }

        // fold distances (reference rounding: (l2 - 2*cl) + c2), ascending k per thread
        #pragma unroll
        for (int r = 0; r < 8; ++r) {
            float l2v = l2s[ty * 8 + r];
            #pragma unroll
            for (int jj = 0; jj < 4; ++jj) {
                unsigned int ulo, uhi;
                UNPACK2(ulo, uhi, acc2[r][jj]);
                float lo = __uint_as_float(ulo);
                float hi = __uint_as_float(uhi);
                int kg = kt * BN + ((jj < 2) ? (tx * 4 + jj * 2) : (128 + tx * 4 + (jj - 2) * 2));
                float s0 = (l2v - 2.0f * lo) + c2sh[kg];
                if (s0 < best[r]) { best[r] = s0; bi[r] = kg; }
                float s1 = (l2v - 2.0f * hi) + c2sh[kg + 1];
                if (s1 < best[r]) { best[r] = s1; bi[r] = kg + 1; }
            }
        }
    }

    // ---- cross-thread argmin per row (first-index tie break) ----
    #pragma unroll
    for (int r = 0; r < 8; ++r) {
        int row = ty * 8 + r;
        redS[row * 33 + tx] = best[r];
        redI[row * 33 + tx] = bi[r];
    }
    __syncthreads();
    if (tid < BM) {
        float b  = redS[tid * 33];
        int   ib = redI[tid * 33];
        #pragma unroll
        for (int t = 1; t < 32; ++t) {
            float s  = redS[tid * 33 + t];
            int   i2 = redI[tid * 33 + t];
            if (s < b || (s == b && i2 < ib)) { b = s; ib = i2; }
        }
        bidx[tid] = ib;
    }
    __syncthreads();

    // ---- update: gather code, straight-through fq, residual, loss ----
    double lacc = 0.0;
    #pragma unroll
    for (int it = 0; it < 16; ++it) {
        int f  = tid + it * NTHREADS;
        int m  = f >> 6;
        int d4 = f & 63;
        size_t off = (size_t)(m0 + m) * DDIM + d4 * 4;
        float4 r4 = *(const float4*)(zin + off);
        float4 c4 = *(const float4*)(cbg + (size_t)bidx[m] * DDIM + d4 * 4);
        float4 fo, rn;
        float4 fprev;
        if (!firstStage) fprev = *(const float4*)(fq + off);

        // exact reference rounding chain per element:
        // t = c - r; st = r + t; fq (+)= st; r_next = r - st; loss += t*t
        {
            float t = c4.x - r4.x; float st = r4.x + t;
            fo.x = firstStage ? st : (fprev.x + st); rn.x = r4.x - st;
            lacc += (double)t * (double)t;
        }
        {
            float t = c4.y - r4.y; float st = r4.y + t;
            fo.y = firstStage ? st : (fprev.y + st); rn.y = r4.y - st;
            lacc += (double)t * (double)t;
        }
        {
            float t = c4.z - r4.z; float st = r4.z + t;
            fo.z = firstStage ? st : (fprev.z + st); rn.z = r4.z - st;
            lacc += (double)t * (double)t;
        }
        {
            float t = c4.w - r4.w; float st = r4.w + t;
            fo.w = firstStage ? st : (fprev.w + st); rn.w = r4.w - st;
            lacc += (double)t * (double)t;
        }
        *(float4*)(fq + off) = fo;
        if (writeR) *(float4*)(rout + off) = rn;
    }

    // warp-reduce loss, one atomic per warp
    #pragma unroll
    for (int o = 16; o; o >>= 1) lacc += __shfl_down_sync(0xffffffffu, lacc, o);
    if ((tid & 31) == 0) atomicAdd(lossp, lacc);
}

// ---------------- finalize: write the two (identical) loss scalars ----------------
__global__ void rvq_finalize_kernel(const double* __restrict__ loss, float* __restrict__ out)
{
    if (blockIdx.x == 0 && threadIdx.x == 0) {
        const double nd = (double)((size_t)NROWS * DDIM);
        float L = 0.f;
        for (int i = 0; i < NCB; ++i) L = L + (float)(loss[i] / nd);  // per-stage mean, summed in fp32 like ref
        out[(size_t)NROWS * DDIM]     = L;  // codebook_losses
        out[(size_t)NROWS * DDIM + 1] = L;  // commitment_losses (numerically identical forward)
    }
}

// ---------------- launch ----------------
extern "C" void kernel_launch(void* const* d_in, const int* in_sizes, int n_in,
                              void* d_out, int out_size)
{
    const float* z  = (const float*)d_in[0];   // [65536, 256]
    const float* cb = (const float*)d_in[1];   // [3, 1024, 256]
    float* out = (float*)d_out;

    float*  res_p  = nullptr;
    float*  c2_p   = nullptr;
    double* loss_p = nullptr;
    cudaGetSymbolAddress((void**)&res_p,  g_res);
    cudaGetSymbolAddress((void**)&c2_p,   g_c2);
    cudaGetSymbolAddress((void**)&loss_p, g_loss);

    cudaFuncSetAttribute(rvq_stage_kernel,
                         cudaFuncAttributeMaxDynamicSharedMemorySize, SMEM_BYTES);

    const int nblk = NROWS / BM;  // 1024

    rvq_init_kernel<<<(NCB * KCB * 32) / NTHREADS, NTHREADS>>>(cb, c2_p, loss_p);

    // stage 0: reads z, writes fq (init) + residual
    rvq_stage_kernel<<<nblk, NTHREADS, SMEM_BYTES>>>(
        z, cb, c2_p, out, res_p, loss_p + 0, /*firstStage=*/1, /*writeR=*/1);
    // stage 1: in-place residual (rows block-exclusive, read-before-write)
    rvq_stage_kernel<<<nblk, NTHREADS, SMEM_BYTES>>>(
        res_p, cb + (size_t)KCB * DDIM, c2_p + KCB, out, res_p, loss_p + 1, 0, 1);
    // stage 2: residual output unused -> skip write
    rvq_stage_kernel<<<nblk, NTHREADS, SMEM_BYTES>>>(
        res_p, cb + (size_t)2 * KCB * DDIM, c2_p + 2 * KCB, out, res_p, loss_p + 2, 0, 0);

    rvq_finalize_kernel<<<1, 32>>>(loss_p, out);
}